// round 2
// baseline (speedup 1.0000x reference)
#include <cuda_runtime.h>
#include <cuda_fp16.h>

#define Bz   128
#define Lz   1000
#define Cz   12
#define Hz   128
#define G4   512
#define DMz  128
#define DIz  256
#define DSz  16
#define DRz  8
#define XDz  40
#define FCz  128
#define NCz  5
#define BLz  (Bz*Lz)   // 128000

// ---------------- static scratch (allocation-free rule) ----------------
__device__ __align__(16) __half2 g_Whh2T[64*512];      // [k][r] pairs of W_hh
__device__ float g_h   [BLz*Hz];                        // LSTM hidden states
__device__ float g_min [BLz*DMz];                       // mamba input
__device__ float g_xz  [(size_t)BLz*512];               // in_proj out (x | z)
__device__ float g_xs  [BLz*DIz];                       // conv+silu out
__device__ float g_xdbl[BLz*XDz];                       // dt | B | C
__device__ float g_delta[BLz*DIz];                      // softplus(dt_proj)
__device__ float g_ybar[Bz*DIz];                        // mean-pooled y

// ---------------- math helpers ----------------
__device__ __forceinline__ float sigf(float x){
    return __fdividef(1.0f, 1.0f + __expf(-x));
}
__device__ __forceinline__ float tanh_f(float x){
    float t = __expf(-2.0f * fabsf(x));               // in (0,1], no overflow
    float r = __fdividef(1.0f - t, 1.0f + t);
    return (x >= 0.0f) ? r : -r;
}
__device__ __forceinline__ float softplusf(float x){
    return (x > 20.0f) ? x : log1pf(__expf(x));
}

// ---------------- prep: W_hh -> fp16 transposed-pair layout ----------------
__global__ void prep_whh(const float* __restrict__ Whh){
    int tid = blockIdx.x * blockDim.x + threadIdx.x;   // k*512 + r
    if (tid < 64*512){
        int k = tid >> 9, r = tid & 511;
        g_Whh2T[tid] = __floats2half2_rn(Whh[r*Hz + 2*k], Whh[r*Hz + 2*k + 1]);
    }
}

// ---------------- LSTM scan: 1 block = 1 batch, 512 threads = gate rows ----------------
__global__ __launch_bounds__(512, 1)
void lstm_kernel(const float* __restrict__ x, const float* __restrict__ Wih,
                 const float* __restrict__ bih, const float* __restrict__ bhh){
    extern __shared__ float sm[];
    __half2* Wsh = (__half2*)sm;            // 32768 half2 = 128KB, layout [k][r]
    float* hsh   = sm + 32768;              // 128
    float* gsh   = hsh + 128;               // 512 gate values
    float* xb    = gsh + 512;               // 2 x 12 double-buffered x row

    const int r = threadIdx.x;
    const int b = blockIdx.x;

    { // stage W into SMEM (vectorized)
        float4* dst = (float4*)Wsh;
        const float4* src = (const float4*)g_Whh2T;
        #pragma unroll
        for (int i = 0; i < 16; i++) dst[r + i*512] = src[r + i*512];
    }
    float wih[Cz];
    #pragma unroll
    for (int c = 0; c < Cz; c++) wih[c] = Wih[r*Cz + c];
    const float bsum = bih[r] + bhh[r];

    float cst = 0.0f;
    if (r < Hz) hsh[r] = 0.0f;
    const float* xg = x + (size_t)b * Lz * Cz;
    if (r < Cz) xb[r] = xg[r];
    __syncthreads();

    float* gho = g_h + (size_t)b * Lz * Hz;

    for (int t = 0; t < Lz; t++){
        const int cur = t & 1;
        float xpre = 0.0f;
        if (r < Cz && t + 1 < Lz) xpre = xg[(t+1)*Cz + r];   // prefetch

        float acc = bsum;
        const float* xc = xb + cur*Cz;
        #pragma unroll
        for (int c = 0; c < Cz; c++) acc = fmaf(wih[c], xc[c], acc);

        const __half2* wr = Wsh + r;   // stride 512 -> conflict-free LDS
        #pragma unroll 8
        for (int k = 0; k < 64; k++){
            float2 w = __half22float2(wr[k*512]);
            acc = fmaf(w.x, hsh[2*k],   acc);
            acc = fmaf(w.y, hsh[2*k+1], acc);
        }
        gsh[r] = acc;
        if (r < Cz && t + 1 < Lz) xb[(cur^1)*Cz + r] = xpre;
        __syncthreads();

        if (r < Hz){
            float ig = sigf(gsh[r]);
            float fg = sigf(gsh[Hz + r]);
            float gg = tanh_f(gsh[2*Hz + r]);
            float og = sigf(gsh[3*Hz + r]);
            cst = fg * cst + ig * gg;
            float hv = og * tanh_f(cst);
            hsh[r] = hv;
            gho[t*Hz + r] = hv;
        }
        __syncthreads();
    }
}

// ---------------- generic fp32 tiled GEMM: C[M,N] = A[M,K] @ W[N,K]^T (+bias) ----------------
__device__ __forceinline__ void gemm_body(const float* __restrict__ A,
                                          const float* __restrict__ W,
                                          const float* __restrict__ bias,
                                          float* __restrict__ C,
                                          int M, int N, int K){
    __shared__ float As[16][65];
    __shared__ float Ws[16][65];
    const int tid = threadIdx.x;
    const int tx = tid & 15, ty = tid >> 4;
    const int bn = blockIdx.x * 64, bm = blockIdx.y * 64;
    const int lrow = tid >> 2, lk = (tid & 3) * 4;

    float acc[4][4] = {};
    const float* Ap  = A + (size_t)(bm + lrow) * K + lk;
    const bool wvalid = (bn + lrow) < N;
    const float* Wpp = W + (size_t)(bn + lrow) * K + lk;

    for (int kb = 0; kb < K; kb += 16){
        float4 av = *(const float4*)(Ap + kb);
        float4 wv = make_float4(0.f, 0.f, 0.f, 0.f);
        if (wvalid) wv = *(const float4*)(Wpp + kb);
        As[lk+0][lrow] = av.x; As[lk+1][lrow] = av.y;
        As[lk+2][lrow] = av.z; As[lk+3][lrow] = av.w;
        Ws[lk+0][lrow] = wv.x; Ws[lk+1][lrow] = wv.y;
        Ws[lk+2][lrow] = wv.z; Ws[lk+3][lrow] = wv.w;
        __syncthreads();
        #pragma unroll
        for (int k = 0; k < 16; k++){
            float a[4], bb[4];
            #pragma unroll
            for (int i = 0; i < 4; i++) a[i]  = As[k][ty*4 + i];
            #pragma unroll
            for (int j = 0; j < 4; j++) bb[j] = Ws[k][tx*4 + j];
            #pragma unroll
            for (int i = 0; i < 4; i++)
                #pragma unroll
                for (int j = 0; j < 4; j++)
                    acc[i][j] = fmaf(a[i], bb[j], acc[i][j]);
        }
        __syncthreads();
    }
    #pragma unroll
    for (int i = 0; i < 4; i++){
        int m = bm + ty*4 + i;
        #pragma unroll
        for (int j = 0; j < 4; j++){
            int n = bn + tx*4 + j;
            if (n < N){
                float v = acc[i][j];
                if (bias) v += bias[n];
                C[(size_t)m * N + n] = v;
            }
        }
    }
}

__global__ void gemm_min_k (const float* w, const float* bp){ gemm_body(g_h,   w, bp,      g_min,  BLz, DMz, Hz ); }
__global__ void gemm_xz_k  (const float* w)                 { gemm_body(g_min, w, nullptr, g_xz,   BLz, 512, DMz); }
__global__ void gemm_xdbl_k(const float* w)                 { gemm_body(g_xs,  w, nullptr, g_xdbl, BLz, XDz, DIz); }

// ---------------- causal depthwise conv (DC=4) + SiLU ----------------
__global__ void conv_silu_kernel(const float* __restrict__ cw, const float* __restrict__ cb){
    const int bl = blockIdx.x;
    const int d  = threadIdx.x;
    const int l  = bl % Lz;
    const int base = bl - l;
    float w0 = cw[d*4+0], w1 = cw[d*4+1], w2 = cw[d*4+2], w3 = cw[d*4+3];
    float acc = cb[d];
    if (l >= 3) acc = fmaf(w0, g_xz[(size_t)(base+l-3)*512 + d], acc);
    if (l >= 2) acc = fmaf(w1, g_xz[(size_t)(base+l-2)*512 + d], acc);
    if (l >= 1) acc = fmaf(w2, g_xz[(size_t)(base+l-1)*512 + d], acc);
    acc = fmaf(w3, g_xz[(size_t)bl*512 + d], acc);
    g_xs[(size_t)bl*DIz + d] = acc * sigf(acc);
}

// ---------------- delta = softplus(dt @ dt_proj^T + b), K=8 ----------------
__global__ void delta_kernel(const float* __restrict__ dtw, const float* __restrict__ dtb){
    const int bl = blockIdx.x;
    const int d  = threadIdx.x;
    __shared__ float dt[DRz];
    if (d < DRz) dt[d] = g_xdbl[(size_t)bl*XDz + d];
    __syncthreads();
    float acc = dtb[d];
    #pragma unroll
    for (int rr = 0; rr < DRz; rr++) acc = fmaf(dt[rr], dtw[d*DRz + rr], acc);
    g_delta[(size_t)bl*DIz + d] = softplusf(acc);
}

// ---------------- selective scan, fused (+xs*D)*silu(z) and mean-pool ----------------
__global__ __launch_bounds__(256, 1)
void scan_kernel(const float* __restrict__ Alog, const float* __restrict__ Dv){
    const int b = blockIdx.x;
    const int d = threadIdx.x;
    __shared__ float BC[2][32];        // [buf][B(16) | C(16)]

    float Aa[DSz];
    #pragma unroll
    for (int s = 0; s < DSz; s++) Aa[s] = -__expf(Alog[d*DSz + s]);
    const float Dd = Dv[d];

    float h[DSz] = {};
    float ysum = 0.0f;

    const float* dp  = g_delta + (size_t)b*Lz*DIz + d;
    const float* xp  = g_xs    + (size_t)b*Lz*DIz + d;
    const float* zp  = g_xz    + (size_t)b*Lz*512 + 256 + d;
    const float* bcp = g_xdbl  + (size_t)b*Lz*XDz + 8;

    float dl = dp[0], xv = xp[0], zv = zp[0];
    if (d < 32) BC[0][d] = bcp[d];
    __syncthreads();

    for (int t = 0; t < Lz; t++){
        const int cur = t & 1;
        float nd = 0.f, nx = 0.f, nz = 0.f;
        if (t + 1 < Lz){   // prefetch next step (hides DRAM latency)
            nd = dp[(size_t)(t+1)*DIz];
            nx = xp[(size_t)(t+1)*DIz];
            nz = zp[(size_t)(t+1)*512];
            if (d < 32) BC[cur^1][d] = bcp[(t+1)*XDz + d];
        }
        float dx = dl * xv;
        float y = 0.0f;
        #pragma unroll
        for (int s = 0; s < DSz; s++){
            float dA = __expf(dl * Aa[s]);
            h[s] = fmaf(dA, h[s], dx * BC[cur][s]);
            y = fmaf(h[s], BC[cur][16 + s], y);
        }
        y = (y + xv * Dd) * (zv * sigf(zv));
        ysum += y;
        __syncthreads();
        dl = nd; xv = nx; zv = nz;
    }
    g_ybar[b*DIz + d] = ysum * (1.0f / (float)Lz);
}

// ---------------- head: out_proj (pool-commuted) -> fc1 relu -> fc2 ----------------
__global__ void head_kernel(const float* __restrict__ opw,
                            const float* __restrict__ f1w, const float* __restrict__ f1b,
                            const float* __restrict__ f2w, const float* __restrict__ f2b,
                            float* __restrict__ out){
    const int b = blockIdx.x;
    const int e = threadIdx.x;   // 128
    __shared__ float yb[DIz];
    __shared__ float pl[DMz];
    __shared__ float hf[FCz];
    yb[e]       = g_ybar[b*DIz + e];
    yb[128 + e] = g_ybar[b*DIz + 128 + e];
    __syncthreads();
    float acc = 0.0f;
    #pragma unroll 8
    for (int dd = 0; dd < DIz; dd++) acc = fmaf(yb[dd], opw[e*DIz + dd], acc);
    pl[e] = acc;
    __syncthreads();
    acc = f1b[e];
    #pragma unroll 8
    for (int dd = 0; dd < DMz; dd++) acc = fmaf(pl[dd], f1w[e*DMz + dd], acc);
    hf[e] = fmaxf(acc, 0.0f);
    __syncthreads();
    if (e < NCz){
        acc = f2b[e];
        #pragma unroll 8
        for (int dd = 0; dd < FCz; dd++) acc = fmaf(hf[dd], f2w[e*FCz + dd], acc);
        out[b*NCz + e] = acc;
    }
}

// ---------------- launch ----------------
extern "C" void kernel_launch(void* const* d_in, const int* in_sizes, int n_in,
                              void* d_out, int out_size){
    const float* x     = (const float*)d_in[0];
    const float* Wih   = (const float*)d_in[1];
    const float* Whh   = (const float*)d_in[2];
    const float* bih   = (const float*)d_in[3];
    const float* bhh   = (const float*)d_in[4];
    const float* Wp    = (const float*)d_in[5];
    const float* bp    = (const float*)d_in[6];
    const float* inpw  = (const float*)d_in[7];
    const float* convw = (const float*)d_in[8];
    const float* convb = (const float*)d_in[9];
    const float* xpw   = (const float*)d_in[10];
    const float* dtw   = (const float*)d_in[11];
    const float* dtb   = (const float*)d_in[12];
    const float* Alog  = (const float*)d_in[13];
    const float* Dv    = (const float*)d_in[14];
    const float* opw   = (const float*)d_in[15];
    const float* f1w   = (const float*)d_in[16];
    const float* f1b   = (const float*)d_in[17];
    const float* f2w   = (const float*)d_in[18];
    const float* f2b   = (const float*)d_in[19];

    const int lstm_smem = 131072 + (128 + 512 + 24) * 4;   // 133728 B
    cudaFuncSetAttribute(lstm_kernel, cudaFuncAttributeMaxDynamicSharedMemorySize, lstm_smem);

    prep_whh<<<128, 256>>>(Whh);
    lstm_kernel<<<Bz, 512, lstm_smem>>>(x, Wih, bih, bhh);
    gemm_min_k <<<dim3(DMz/64, BLz/64), 256>>>(Wp, bp);
    gemm_xz_k  <<<dim3(512/64, BLz/64), 256>>>(inpw);
    conv_silu_kernel<<<BLz, DIz>>>(convw, convb);
    gemm_xdbl_k<<<dim3(1, BLz/64), 256>>>(xpw);
    delta_kernel<<<BLz, DIz>>>(dtw, dtb);
    scan_kernel<<<Bz, DIz>>>(Alog, Dv);
    head_kernel<<<Bz, 128>>>(opw, f1w, f1b, f2w, f2b, (float*)d_out);
}

// round 6
// speedup vs baseline: 1.5870x; 1.5870x over previous
#include <cuda_runtime.h>
#include <cuda_fp16.h>

#define Bz   128
#define Lz   1000
#define Cz   12
#define Hz   128
#define DMz  128
#define DIz  256
#define DSz  16
#define DRz  8
#define XDz  40
#define FCz  128
#define NCz  5
#define BLz  (Bz*Lz)   // 128000

// ---------------- static scratch (allocation-free rule) ----------------
__device__ __align__(16) __half2 g_Whh2[512*64];        // [r][k] pairs of W_hh (fp16)
__device__ __align__(16) __half  g_Wp16 [128*128];      // Wp fp16
__device__ __align__(16) __half  g_inpw16[512*128];     // in_proj_w fp16
__device__ __align__(16) __half  g_h16  [(size_t)BLz*Hz];   // LSTM hidden (fp16)
__device__ __align__(16) __half  g_min16[(size_t)BLz*DMz];  // mamba input (fp16)
__device__ float g_xz  [(size_t)BLz*512];               // in_proj out (x | z) fp32
__device__ float g_xs  [BLz*DIz];                       // conv+silu out
__device__ float g_xdbl[BLz*XDz];                       // dt | B | C
__device__ float g_delta[BLz*DIz];                      // softplus(dt_proj)
__device__ float g_ybar[Bz*DIz];                        // mean-pooled y

// ---------------- math helpers ----------------
__device__ __forceinline__ float sigf(float x){
    return __fdividef(1.0f, 1.0f + __expf(-x));
}
__device__ __forceinline__ float tanh_f(float x){
    float t = __expf(-2.0f * fabsf(x));
    float r = __fdividef(1.0f - t, 1.0f + t);
    return (x >= 0.0f) ? r : -r;
}
__device__ __forceinline__ float softplusf(float x){
    return (x > 20.0f) ? x : log1pf(__expf(x));
}
__device__ __forceinline__ unsigned smem_u32(const void* p){
    return (unsigned)__cvta_generic_to_shared(p);
}

// ---------------- mma / ldmatrix wrappers ----------------
__device__ __forceinline__ void mma16816(float c[4], const unsigned a[4], const unsigned b[2]){
    asm volatile("mma.sync.aligned.m16n8k16.row.col.f32.f16.f16.f32 "
        "{%0,%1,%2,%3}, {%4,%5,%6,%7}, {%8,%9}, {%0,%1,%2,%3};\n"
        : "+f"(c[0]), "+f"(c[1]), "+f"(c[2]), "+f"(c[3])
        : "r"(a[0]), "r"(a[1]), "r"(a[2]), "r"(a[3]), "r"(b[0]), "r"(b[1]));
}
__device__ __forceinline__ void ldsm_x4(unsigned r[4], unsigned addr){
    asm volatile("ldmatrix.sync.aligned.m8n8.x4.shared.b16 {%0,%1,%2,%3}, [%4];\n"
        : "=r"(r[0]), "=r"(r[1]), "=r"(r[2]), "=r"(r[3]) : "r"(addr));
}
__device__ __forceinline__ void ldsm_x2(unsigned r[2], unsigned addr){
    asm volatile("ldmatrix.sync.aligned.m8n8.x2.shared.b16 {%0,%1}, [%2];\n"
        : "=r"(r[0]), "=r"(r[1]) : "r"(addr));
}

// ---------------- prep: fp16 weight conversions ----------------
__global__ void prep_all(const float* __restrict__ Whh, const float* __restrict__ Wp,
                         const float* __restrict__ inpw){
    int i = blockIdx.x * 256 + threadIdx.x;
    if (i < 512*64){
        int r = i >> 6, k = i & 63;
        g_Whh2[i] = __floats2half2_rn(Whh[r*Hz + 2*k], Whh[r*Hz + 2*k + 1]);
    }
    if (i < 128*128) g_Wp16[i]  = __float2half(Wp[i]);
    if (i < 512*128) g_inpw16[i] = __float2half(inpw[i]);
}

// ---------------- LSTM scan: weights in registers, fp16 HFMA2 ----------------
__global__ __launch_bounds__(512, 1)
void lstm_kernel(const float* __restrict__ x, const float* __restrict__ Wih,
                 const float* __restrict__ bih, const float* __restrict__ bhh){
    __shared__ __align__(16) __half h16s[Hz];
    __shared__ float gsh[512];
    __shared__ float xb[2][Cz];

    const int r = threadIdx.x;
    const int b = blockIdx.x;

    __half2 w[64];
    #pragma unroll
    for (int k = 0; k < 64; k++) w[k] = g_Whh2[r*64 + k];
    float wih[Cz];
    #pragma unroll
    for (int c = 0; c < Cz; c++) wih[c] = Wih[r*Cz + c];
    const float bsum = bih[r] + bhh[r];

    float cst = 0.0f;
    if (r < Hz) h16s[r] = __float2half(0.0f);
    const float* xg = x + (size_t)b * Lz * Cz;
    if (r < Cz) xb[0][r] = xg[r];
    __syncthreads();

    __half* gho = g_h16 + (size_t)b * Lz * Hz;

    for (int t = 0; t < Lz; t++){
        const int cur = t & 1;
        float xpre = (r < Cz && t + 1 < Lz) ? xg[(t+1)*Cz + r] : 0.0f;

        float acc = bsum;
        #pragma unroll
        for (int c = 0; c < Cz; c++) acc = fmaf(wih[c], xb[cur][c], acc);

        __half2 s0 = __floats2half2_rn(0.f, 0.f), s1 = s0, s2 = s0, s3 = s0;
        const uint4* hp = (const uint4*)h16s;    // uniform addresses -> LDS broadcast
        #pragma unroll
        for (int i = 0; i < 16; i++){
            uint4 hv = hp[i];
            s0 = __hfma2(w[4*i+0], *(__half2*)&hv.x, s0);
            s1 = __hfma2(w[4*i+1], *(__half2*)&hv.y, s1);
            s2 = __hfma2(w[4*i+2], *(__half2*)&hv.z, s2);
            s3 = __hfma2(w[4*i+3], *(__half2*)&hv.w, s3);
        }
        float2 f0 = __half22float2(__hadd2(s0, s1));
        float2 f1 = __half22float2(__hadd2(s2, s3));
        gsh[r] = acc + (f0.x + f0.y) + (f1.x + f1.y);
        if (r < Cz && t + 1 < Lz) xb[cur^1][r] = xpre;
        __syncthreads();

        if (r < Hz){
            float ig = sigf(gsh[r]);
            float fg = sigf(gsh[Hz + r]);
            float gg = tanh_f(gsh[2*Hz + r]);
            float og = sigf(gsh[3*Hz + r]);
            cst = fg * cst + ig * gg;
            float hv = og * tanh_f(cst);
            __half hh = __float2half(hv);
            h16s[r] = hh;
            gho[t*Hz + r] = hh;
        }
        __syncthreads();
    }
}

// ---------------- fp16 tensor-core GEMM: C[M,N] = A[M,K] @ W[N,K]^T ----------------
// 128x64 tile, 256 threads (8 warps: 4 m x 2 n), m16n8k16, double-buffered smem.
#define AST 24
#define BST 24
template<bool BIAS, bool OUTH>
__device__ __forceinline__ void gemm16_body(const __half* __restrict__ A,
        const __half* __restrict__ W, const float* __restrict__ bias,
        float* __restrict__ Cf, __half* __restrict__ Ch,
        int M, int N, int K){
    __shared__ __align__(16) __half As[2][128*AST];
    __shared__ __align__(16) __half Bs[2][64*BST];
    const int tid  = threadIdx.x;
    const int lane = tid & 31, wid = tid >> 5;
    const int wm = (wid & 3) * 32, wn = (wid >> 2) * 32;
    const int bm = blockIdx.y * 128, bn = blockIdx.x * 64;

    const int ar = tid >> 1, ak = (tid & 1) * 8;
    const __half* Ag = A + (size_t)(bm + ar) * K + ak;
    const int br = (tid & 127) >> 1, bk = (tid & 1) * 8;
    const __half* Bg = W + (size_t)(bn + br) * K + bk;

    uint4 av = *(const uint4*)Ag;
    uint4 bv = make_uint4(0,0,0,0);
    if (tid < 128) bv = *(const uint4*)Bg;
    *(uint4*)&As[0][ar*AST + ak] = av;
    if (tid < 128) *(uint4*)&Bs[0][br*BST + bk] = bv;
    __syncthreads();

    const int al = lane & 15, ac = (lane >> 4) * 8;
    const int bl = lane & 7,  bc = ((lane >> 3) & 1) * 8;

    float c[2][4][4] = {};
    const int KS = K >> 4;
    for (int ks = 0; ks < KS; ks++){
        const int buf = ks & 1;
        if (ks + 1 < KS){
            av = *(const uint4*)(Ag + (ks+1)*16);
            if (tid < 128) bv = *(const uint4*)(Bg + (ks+1)*16);
        }
        unsigned afr[2][4], bfr[4][2];
        #pragma unroll
        for (int mf = 0; mf < 2; mf++)
            ldsm_x4(afr[mf], smem_u32(&As[buf][(wm + mf*16 + al)*AST + ac]));
        #pragma unroll
        for (int nf = 0; nf < 4; nf++)
            ldsm_x2(bfr[nf], smem_u32(&Bs[buf][(wn + nf*8 + bl)*BST + bc]));
        #pragma unroll
        for (int mf = 0; mf < 2; mf++)
            #pragma unroll
            for (int nf = 0; nf < 4; nf++)
                mma16816(c[mf][nf], afr[mf], bfr[nf]);
        if (ks + 1 < KS){
            *(uint4*)&As[buf^1][ar*AST + ak] = av;
            if (tid < 128) *(uint4*)&Bs[buf^1][br*BST + bk] = bv;
            __syncthreads();
        }
    }
    #pragma unroll
    for (int mf = 0; mf < 2; mf++){
        #pragma unroll
        for (int nf = 0; nf < 4; nf++){
            int row0 = bm + wm + mf*16 + (lane >> 2);
            int col0 = bn + wn + nf*8 + (lane & 3)*2;
            #pragma unroll
            for (int i = 0; i < 2; i++){
                float v0 = c[mf][nf][i*2+0], v1 = c[mf][nf][i*2+1];
                int rr = row0 + i*8;
                if (BIAS){ v0 += bias[col0]; v1 += bias[col0+1]; }
                if (OUTH){
                    *(__half2*)&Ch[(size_t)rr*N + col0] = __floats2half2_rn(v0, v1);
                } else {
                    Cf[(size_t)rr*N + col0]     = v0;
                    Cf[(size_t)rr*N + col0 + 1] = v1;
                }
            }
        }
    }
}

__global__ void gemm16_min(const float* __restrict__ bp){
    gemm16_body<true, true >(g_h16,   g_Wp16,   bp,      nullptr, g_min16, BLz, 128, 128);
}
__global__ void gemm16_xz(){
    gemm16_body<false, false>(g_min16, g_inpw16, nullptr, g_xz,    nullptr, BLz, 512, 128);
}

// ---------------- fp32 SIMT GEMM (kept for x_proj; feeds exp-sensitive path) ----------------
__device__ __forceinline__ void gemm_body(const float* __restrict__ A,
                                          const float* __restrict__ W,
                                          float* __restrict__ C,
                                          int M, int N, int K){
    __shared__ float As[16][65];
    __shared__ float Ws[16][65];
    const int tid = threadIdx.x;
    const int tx = tid & 15, ty = tid >> 4;
    const int bn = blockIdx.x * 64, bm = blockIdx.y * 64;
    const int lrow = tid >> 2, lk = (tid & 3) * 4;

    float acc[4][4] = {};
    const float* Ap  = A + (size_t)(bm + lrow) * K + lk;
    const bool wvalid = (bn + lrow) < N;
    const float* Wpp = W + (size_t)(bn + lrow) * K + lk;

    for (int kb = 0; kb < K; kb += 16){
        float4 av = *(const float4*)(Ap + kb);
        float4 wv = make_float4(0.f, 0.f, 0.f, 0.f);
        if (wvalid) wv = *(const float4*)(Wpp + kb);
        As[lk+0][lrow] = av.x; As[lk+1][lrow] = av.y;
        As[lk+2][lrow] = av.z; As[lk+3][lrow] = av.w;
        Ws[lk+0][lrow] = wv.x; Ws[lk+1][lrow] = wv.y;
        Ws[lk+2][lrow] = wv.z; Ws[lk+3][lrow] = wv.w;
        __syncthreads();
        #pragma unroll
        for (int k = 0; k < 16; k++){
            float a[4], bb[4];
            #pragma unroll
            for (int i = 0; i < 4; i++) a[i]  = As[k][ty*4 + i];
            #pragma unroll
            for (int j = 0; j < 4; j++) bb[j] = Ws[k][tx*4 + j];
            #pragma unroll
            for (int i = 0; i < 4; i++)
                #pragma unroll
                for (int j = 0; j < 4; j++)
                    acc[i][j] = fmaf(a[i], bb[j], acc[i][j]);
        }
        __syncthreads();
    }
    #pragma unroll
    for (int i = 0; i < 4; i++){
        int m = bm + ty*4 + i;
        #pragma unroll
        for (int j = 0; j < 4; j++){
            int n = bn + tx*4 + j;
            if (n < N) C[(size_t)m * N + n] = acc[i][j];
        }
    }
}
__global__ void gemm_xdbl_k(const float* w){ gemm_body(g_xs, w, g_xdbl, BLz, XDz, DIz); }

// ---------------- causal depthwise conv (DC=4) + SiLU ----------------
__global__ void conv_silu_kernel(const float* __restrict__ cw, const float* __restrict__ cb){
    const int bl = blockIdx.x;
    const int d  = threadIdx.x;
    const int l  = bl % Lz;
    const int base = bl - l;
    float w0 = cw[d*4+0], w1 = cw[d*4+1], w2 = cw[d*4+2], w3 = cw[d*4+3];
    float acc = cb[d];
    if (l >= 3) acc = fmaf(w0, g_xz[(size_t)(base+l-3)*512 + d], acc);
    if (l >= 2) acc = fmaf(w1, g_xz[(size_t)(base+l-2)*512 + d], acc);
    if (l >= 1) acc = fmaf(w2, g_xz[(size_t)(base+l-1)*512 + d], acc);
    acc = fmaf(w3, g_xz[(size_t)bl*512 + d], acc);
    g_xs[(size_t)bl*DIz + d] = acc * sigf(acc);
}

// ---------------- delta = softplus(dt @ dt_proj^T + b), K=8 ----------------
__global__ void delta_kernel(const float* __restrict__ dtw, const float* __restrict__ dtb){
    const int bl = blockIdx.x;
    const int d  = threadIdx.x;
    __shared__ float dt[DRz];
    if (d < DRz) dt[d] = g_xdbl[(size_t)bl*XDz + d];
    __syncthreads();
    float acc = dtb[d];
    #pragma unroll
    for (int rr = 0; rr < DRz; rr++) acc = fmaf(dt[rr], dtw[d*DRz + rr], acc);
    g_delta[(size_t)bl*DIz + d] = softplusf(acc);
}

// ---------------- selective scan, fused (+xs*D)*silu(z) and mean-pool ----------------
__global__ __launch_bounds__(256, 1)
void scan_kernel(const float* __restrict__ Alog, const float* __restrict__ Dv){
    const int b = blockIdx.x;
    const int d = threadIdx.x;
    __shared__ float BC[2][32];

    float Aa[DSz];
    #pragma unroll
    for (int s = 0; s < DSz; s++) Aa[s] = -__expf(Alog[d*DSz + s]);
    const float Dd = Dv[d];

    float h[DSz] = {};
    float ysum = 0.0f;

    const float* dp  = g_delta + (size_t)b*Lz*DIz + d;
    const float* xp  = g_xs    + (size_t)b*Lz*DIz + d;
    const float* zp  = g_xz    + (size_t)b*Lz*512 + 256 + d;
    const float* bcp = g_xdbl  + (size_t)b*Lz*XDz + 8;

    float dl = dp[0], xv = xp[0], zv = zp[0];
    if (d < 32) BC[0][d] = bcp[d];
    __syncthreads();

    for (int t = 0; t < Lz; t++){
        const int cur = t & 1;
        float nd = 0.f, nx = 0.f, nz = 0.f;
        if (t + 1 < Lz){
            nd = dp[(size_t)(t+1)*DIz];
            nx = xp[(size_t)(t+1)*DIz];
            nz = zp[(size_t)(t+1)*512];
            if (d < 32) BC[cur^1][d] = bcp[(t+1)*XDz + d];
        }
        float dx = dl * xv;
        float y = 0.0f;
        #pragma unroll
        for (int s = 0; s < DSz; s++){
            float dA = __expf(dl * Aa[s]);
            h[s] = fmaf(dA, h[s], dx * BC[cur][s]);
            y = fmaf(h[s], BC[cur][16 + s], y);
        }
        y = (y + xv * Dd) * (zv * sigf(zv));
        ysum += y;
        __syncthreads();
        dl = nd; xv = nx; zv = nz;
    }
    g_ybar[b*DIz + d] = ysum * (1.0f / (float)Lz);
}

// ---------------- head: out_proj (pool-commuted) -> fc1 relu -> fc2 ----------------
__global__ void head_kernel(const float* __restrict__ opw,
                            const float* __restrict__ f1w, const float* __restrict__ f1b,
                            const float* __restrict__ f2w, const float* __restrict__ f2b,
                            float* __restrict__ out){
    const int b = blockIdx.x;
    const int e = threadIdx.x;   // 128
    __shared__ float yb[DIz];
    __shared__ float pl[DMz];
    __shared__ float hf[FCz];
    yb[e]       = g_ybar[b*DIz + e];
    yb[128 + e] = g_ybar[b*DIz + 128 + e];
    __syncthreads();
    float acc = 0.0f;
    #pragma unroll 8
    for (int dd = 0; dd < DIz; dd++) acc = fmaf(yb[dd], opw[e*DIz + dd], acc);
    pl[e] = acc;
    __syncthreads();
    acc = f1b[e];
    #pragma unroll 8
    for (int dd = 0; dd < DMz; dd++) acc = fmaf(pl[dd], f1w[e*DMz + dd], acc);
    hf[e] = fmaxf(acc, 0.0f);
    __syncthreads();
    if (e < NCz){
        acc = f2b[e];
        #pragma unroll 8
        for (int dd = 0; dd < FCz; dd++) acc = fmaf(hf[dd], f2w[e*FCz + dd], acc);
        out[b*NCz + e] = acc;
    }
}

// ---------------- launch ----------------
extern "C" void kernel_launch(void* const* d_in, const int* in_sizes, int n_in,
                              void* d_out, int out_size){
    const float* x     = (const float*)d_in[0];
    const float* Wih   = (const float*)d_in[1];
    const float* Whh   = (const float*)d_in[2];
    const float* bih   = (const float*)d_in[3];
    const float* bhh   = (const float*)d_in[4];
    const float* Wp    = (const float*)d_in[5];
    const float* bp    = (const float*)d_in[6];
    const float* inpw  = (const float*)d_in[7];
    const float* convw = (const float*)d_in[8];
    const float* convb = (const float*)d_in[9];
    const float* xpw   = (const float*)d_in[10];
    const float* dtw   = (const float*)d_in[11];
    const float* dtb   = (const float*)d_in[12];
    const float* Alog  = (const float*)d_in[13];
    const float* Dv    = (const float*)d_in[14];
    const float* opw   = (const float*)d_in[15];
    const float* f1w   = (const float*)d_in[16];
    const float* f1b   = (const float*)d_in[17];
    const float* f2w   = (const float*)d_in[18];
    const float* f2b   = (const float*)d_in[19];

    prep_all<<<256, 256>>>(Whh, Wp, inpw);
    lstm_kernel<<<Bz, 512>>>(x, Wih, bih, bhh);
    gemm16_min<<<dim3(2, BLz/128), 256>>>(bp);
    gemm16_xz <<<dim3(8, BLz/128), 256>>>();
    conv_silu_kernel<<<BLz, DIz>>>(convw, convb);
    gemm_xdbl_k<<<dim3(1, BLz/64), 256>>>(xpw);
    delta_kernel<<<BLz, DIz>>>(dtw, dtb);
    scan_kernel<<<Bz, DIz>>>(Alog, Dv);
    head_kernel<<<Bz, 128>>>(opw, f1w, f1b, f2w, f2b, (float*)d_out);
}